// round 14
// baseline (speedup 1.0000x reference)
#include <cuda_runtime.h>
#include <math.h>

#define BB 16
#define HH 512
#define WW 512
#define NTOT (BB * HH * WW)

#define RAD 10
#define TILE_H 32
#define TILE_W 64
#define SROWS (TILE_H + 2 * RAD)  // 52
#define GX (WW / TILE_W)          // 8
#define GYT (HH / TILE_H)         // 16
#define NB (GX * GYT * BB)        // 2048
#define SENTW 0x64646464u         // four u8 bytes of 100

// Scratch (no allocation allowed in kernel_launch)
__device__ unsigned char g_f2[NTOT];  // horizontal distance^2 (<=100), u8
__device__ float g_pl[NB];
__device__ float g_pf[NB];
__device__ unsigned g_done = 0;  // last-block counter (self-resetting)

// ---------------------------------------------------------------------------
// K1: one WARP per image row, streaming tgt once. Each lane: 16 cols ->
// 16-bit fg mask; neighbor masks via 2 shfls; per-col horizontal distance f
// (clamped to 10: d>=10 -> heatmap <= exp(-100/8)=3.7e-6 ~ 0, loss-equiv)
// via clz/ffs on a 21-bit window. Stores f^2 as u8 (exact ints <= 100).
// The bit math rides the tgt stream (mask-only K1 measured 88% idle issue).
// ---------------------------------------------------------------------------
__global__ __launch_bounds__(256) void k1_f2(const float* __restrict__ tgt) {
    const int gid = blockIdx.x * 256 + threadIdx.x;
    const int row = gid >> 5;
    const int lane = gid & 31;
    const float4* p = (const float4*)(tgt + (size_t)row * WW + lane * 16);
    float4 v0 = p[0], v1 = p[1], v2 = p[2], v3 = p[3];

    unsigned m = 0;
    m |= (v0.x > 0.5f) ? 1u << 0 : 0u;
    m |= (v0.y > 0.5f) ? 1u << 1 : 0u;
    m |= (v0.z > 0.5f) ? 1u << 2 : 0u;
    m |= (v0.w > 0.5f) ? 1u << 3 : 0u;
    m |= (v1.x > 0.5f) ? 1u << 4 : 0u;
    m |= (v1.y > 0.5f) ? 1u << 5 : 0u;
    m |= (v1.z > 0.5f) ? 1u << 6 : 0u;
    m |= (v1.w > 0.5f) ? 1u << 7 : 0u;
    m |= (v2.x > 0.5f) ? 1u << 8 : 0u;
    m |= (v2.y > 0.5f) ? 1u << 9 : 0u;
    m |= (v2.z > 0.5f) ? 1u << 10 : 0u;
    m |= (v2.w > 0.5f) ? 1u << 11 : 0u;
    m |= (v3.x > 0.5f) ? 1u << 12 : 0u;
    m |= (v3.y > 0.5f) ? 1u << 13 : 0u;
    m |= (v3.z > 0.5f) ? 1u << 14 : 0u;
    m |= (v3.w > 0.5f) ? 1u << 15 : 0u;

    unsigned left = __shfl_up_sync(0xffffffffu, m, 1);
    unsigned right = __shfl_down_sync(0xffffffffu, m, 1);
    if (lane == 0) left = 0;
    if (lane == 31) right = 0;
    unsigned long long w = (unsigned long long)left |
                           ((unsigned long long)m << 16) |
                           ((unsigned long long)right << 32);

    unsigned ow[4];
#pragma unroll
    for (int k = 0; k < 4; k++) {
        unsigned bw = 0;
#pragma unroll
        for (int u = 0; u < 4; u++) {
            int pcol = 4 * k + u;
            unsigned win = (unsigned)(w >> (pcol + 6)) & 0x1FFFFFu;  // p-10..p+10
            unsigned wl = win & 0x7FFu;          // p-10..p (bit10 = center)
            int dl = __clz(wl) - 21;             // 0..11
            unsigned wr = (win >> 10) | 0x800u;  // p..p+10 + sentinel
            int dr = __ffs((int)wr) - 1;         // 0..11
            int f = min(min(dl, dr), 10);
            bw |= (unsigned)(f * f) << (8 * u);
        }
        ow[k] = bw;
    }
    *(uint4*)(g_f2 + (size_t)row * WW + lane * 16) =
        make_uint4(ow[0], ow[1], ow[2], ow[3]);
}

// ---------------------------------------------------------------------------
// K2: per 32x64 tile, fused vertical pass + loss.
//  0) prefetch this thread's 8 inp px (2 LDG.128, blockIdx-only addresses)
//  1) stage f^2 u8 halo (52 rows x 16 words) via uint4 loads; per-row
//     activity flags from one loader-warp ballot (row active iff any byte
//     < 100) — no atomics, no re-reads
//  2) per compute-warp 24-bit activity mask via one ballot over the flags;
//     sparse tap loop (~2 avg): SIMD u8 min-plus, 4 cols per
//     vminu4(vaddus4(v, w*0x01010101)), w = min(dm^2,100) (clamps
//     out-of-window taps; saturating add is safe; init 100 = sentinel)
//  3) branch-free select epilogue on prefetched inp: pos=(d==0) exact;
//     h=exp(-d/8); a=pos?0.85:0.15; s=pos?q:p; e=pos?q:(p-h);
//     focal=a*s^2; loss=focal*e^2
//  4) shuffle reduce; last block folds the final scalar.
// ---------------------------------------------------------------------------
__global__ __launch_bounds__(256) void k2_main(const float* __restrict__ inp,
                                               float* __restrict__ out) {
    const int tid = threadIdx.x;
    const int tx = tid & 31;
    const int wid = tid >> 5;
    const int wc = tx & 15;   // word-col: cols wc*4 .. wc*4+3
    const int s = tx >> 4;    // row-pair selector within warp
    const int r0 = wid * 4;   // warp's first tile row
    const int j0 = blockIdx.x * TILE_W;
    const int i0 = blockIdx.y * TILE_H;
    const int b = blockIdx.z;

    __shared__ __align__(16) unsigned sf2[SROWS][16];  // 3.3 KB
    __shared__ unsigned char srowact[SROWS];
    __shared__ float swF[8];
    __shared__ float swL[8];
    __shared__ int slast;
    __shared__ double sred[512];

    // --- 0) prefetch inp: rows i0+r0+2s, +1; cols j0+4wc.. ---
    const float* ibase = inp + ((size_t)(b * HH + i0 + r0 + 2 * s)) * WW + j0 + wc * 4;
    float4 xa = *(const float4*)ibase;
    float4 xb = *(const float4*)(ibase + WW);

    // --- 1) stage halo + row-activity flags ---
    {
        int rr = tid >> 2;   // 0..63 (rows >= 52 idle)
        int qd = tid & 3;    // uint4 quadrant (4 words = 16 cols)
        uint4 v = make_uint4(SENTW, SENTW, SENTW, SENTW);
        int gr = i0 - RAD + rr;
        bool inr = (rr < SROWS) && ((unsigned)gr < HH);
        if (inr)
            v = *(const uint4*)(g_f2 + ((size_t)(b * HH + gr)) * WW + j0 + qd * 16);
        if (rr < SROWS) ((uint4*)&sf2[rr][0])[qd] = v;
        bool actp = inr && (((v.x ^ SENTW) | (v.y ^ SENTW) | (v.z ^ SENTW) |
                             (v.w ^ SENTW)) != 0u);
        unsigned blt = __ballot_sync(0xffffffffu, actp);
        if (tx < 8) {
            int row = wid * 8 + tx;  // loader-warp covers 8 rows
            if (row < SROWS)
                srowact[row] = (unsigned char)((blt >> (4 * tx)) & 0xFu);
        }
    }
    __syncthreads();

    // --- 2) warp activity ballot + sparse SIMD tap loop ---
    bool act = (tx < 24) ? (srowact[r0 + tx] != 0) : false;
    unsigned rm = __ballot_sync(0xffffffffu, act) & 0xFFFFFFu;

    unsigned acc0 = SENTW, acc1 = SENTW;
    while (rm) {
        int t = __ffs(rm) - 1;
        rm &= rm - 1;
        unsigned v = sf2[r0 + t][wc];
        int dm0 = t - 2 * s - 10;
        int w0 = min(dm0 * dm0, 100);
        acc0 = __vminu4(acc0, __vaddus4(v, (unsigned)w0 * 0x01010101u));
        int dm1 = dm0 - 1;
        int w1 = min(dm1 * dm1, 100);
        acc1 = __vminu4(acc1, __vaddus4(v, (unsigned)w1 * 0x01010101u));
    }

    // --- 3) branch-free select epilogue ---
    float fsum = 0.0f, lsum = 0.0f;
#define PXE(accw, k, xv)                                      \
    {                                                         \
        int d = ((accw) >> (8 * (k))) & 255;                  \
        float h = __expf((float)d * -0.125f);                 \
        bool pos = (d == 0);                                  \
        float p = __fdividef(1.0f, 1.0f + __expf(-(xv)));     \
        float qq = 1.0f - p;                                  \
        float a = pos ? 0.85f : 0.15f;                        \
        float ss = pos ? qq : p;                              \
        float e = pos ? qq : (p - h);                         \
        float f = a * ss * ss;                                \
        fsum += f;                                            \
        lsum = fmaf(f * e, e, lsum);                          \
    }
    PXE(acc0, 0, xa.x) PXE(acc0, 1, xa.y) PXE(acc0, 2, xa.z) PXE(acc0, 3, xa.w)
    PXE(acc1, 0, xb.x) PXE(acc1, 1, xb.y) PXE(acc1, 2, xb.z) PXE(acc1, 3, xb.w)
#undef PXE

    // --- 4) shuffle reduction (fixed order -> deterministic) ---
    float thF = fsum, thL = lsum;
#pragma unroll
    for (int off = 16; off > 0; off >>= 1) {
        thF += __shfl_xor_sync(0xffffffffu, thF, off);
        thL += __shfl_xor_sync(0xffffffffu, thL, off);
    }
    if (tx == 0) {
        swF[wid] = thF;
        swL[wid] = thL;
    }
    __syncthreads();

    const int bid = blockIdx.x + GX * (blockIdx.y + GYT * blockIdx.z);
    if (tid == 0) {
        float F = 0.0f, Lv = 0.0f;
#pragma unroll
        for (int w = 0; w < 8; w++) {
            F += swF[w];
            Lv += swL[w];
        }
        g_pf[bid] = F;
        g_pl[bid] = Lv;
        __threadfence();
        unsigned old = atomicAdd(&g_done, 1u);
        slast = (old == NB - 1) ? 1 : 0;
    }
    __syncthreads();

    // --- last block: fold final scalar ---
    if (slast) {
        __threadfence();
        double* sFd = sred;
        double* sLd = sred + 256;
        double f = 0.0, l = 0.0;
        for (int i = tid; i < NB; i += 256) {
            f += (double)g_pf[i];
            l += (double)g_pl[i];
        }
        sFd[tid] = f;
        sLd[tid] = l;
        __syncthreads();
#pragma unroll
        for (int st = 128; st > 0; st >>= 1) {
            if (tid < st) {
                sFd[tid] += sFd[tid + st];
                sLd[tid] += sLd[tid + st];
            }
            __syncthreads();
        }
        if (tid == 0) {
            double n = (double)NTOT;
            double denom = sFd[0] / n + 0.01;
            out[0] = (float)(2.0 * (sLd[0] / n) / denom);
            g_done = 0;  // reset for next graph replay
        }
    }
}

extern "C" void kernel_launch(void* const* d_in, const int* in_sizes, int n_in,
                              void* d_out, int out_size) {
    const float* inp = (const float*)d_in[0];
    const float* tgt = (const float*)d_in[1];
    float* out = (float*)d_out;

    k1_f2<<<(BB * HH * 32) / 256, 256>>>(tgt);
    dim3 g2(GX, GYT, BB);
    k2_main<<<g2, 256>>>(inp, out);
}